// round 3
// baseline (speedup 1.0000x reference)
#include <cuda_runtime.h>
#include <cuda_fp16.h>
#include <math.h>

#define NFFT    8192
#define LSEQ    4095
#define DMODEL  768
#define NLAYERS 12
#define TTHR    512
#define SPAD    8448                      // 8192 + 8192/32 padding
#define AP(p)   ((p) + ((p) >> 5))
#define CONV_SMEM  ((SPAD + 4096) * sizeof(float2))
#define WSPEC_SMEM (SPAD * sizeof(float2))

// ---------------- device scratch ----------------
__device__ float2 g_x[DMODEL * LSEQ];                      // packed {b0,b1}, (D,L)
__device__ uint2  g_w[(size_t)NLAYERS * DMODEL * 4096];    // fp16 spectra, conv-coalesced order, 302 MB
__device__ float2 g_tw[512];                               // W_8192^k

// ---------------- complex helpers ----------------
__device__ __forceinline__ float2 cadd(float2 a, float2 b) { return make_float2(a.x + b.x, a.y + b.y); }
__device__ __forceinline__ float2 csub(float2 a, float2 b) { return make_float2(a.x - b.x, a.y - b.y); }
__device__ __forceinline__ float2 cmul(float2 a, float2 b) {
    return make_float2(fmaf(a.x, b.x, -a.y * b.y), fmaf(a.x, b.y, a.y * b.x));
}
__device__ __forceinline__ float2 cmulf(float2 a, float c, float s) {
    return make_float2(fmaf(a.x, c, -a.y * s), fmaf(a.x, s, a.y * c));
}
__device__ __forceinline__ float2 conjf(float2 a) { return make_float2(a.x, -a.y); }
__device__ __forceinline__ float2 h2f2(unsigned u) {
    __half2 h = *reinterpret_cast<__half2*>(&u);
    return __half22float2(h);
}
__device__ __forceinline__ unsigned f2h2(float2 v) {
    __half2 h = __floats2half2_rn(v.x, v.y);
    return *reinterpret_cast<unsigned*>(&h);
}

// 4-bit bit reversal (involution)
__device__ __forceinline__ constexpr int br4c(int r) {
    return ((r & 1) << 3) | ((r & 2) << 1) | ((r & 4) >> 1) | ((r & 8) >> 3);
}

// multiply by W16^k (forward) or conj (inverse)
__device__ __forceinline__ float2 twk(float2 a, int k, bool cj) {
    const float c1 = 0.92387953251128675613f;
    const float s1 = 0.38268343236508977173f;
    const float r2 = 0.70710678118654752440f;
    float c, s;
    switch (k & 7) {
        case 0: return a;
        case 1: c =  c1; s = -s1; break;
        case 2: c =  r2; s = -r2; break;
        case 3: c =  s1; s = -c1; break;
        case 4: return cj ? make_float2(-a.y, a.x) : make_float2(a.y, -a.x);
        case 5: c = -s1; s = -c1; break;
        case 6: c = -r2; s = -r2; break;
        default: c = -c1; s = -s1; break;
    }
    if (cj) s = -s;
    return cmulf(a, c, s);
}

// forward DIF DFT16: natural input, slot q holds X[br4(q)]
__device__ __forceinline__ void dft16_dif(float2* v) {
    #pragma unroll
    for (int i = 0; i < 8; i++) {
        float2 a = v[i], b = v[i + 8];
        v[i] = cadd(a, b); v[i + 8] = twk(csub(a, b), i, false);
    }
    #pragma unroll
    for (int B = 0; B < 16; B += 8)
        #pragma unroll
        for (int i = 0; i < 4; i++) {
            float2 a = v[B + i], b = v[B + i + 4];
            v[B + i] = cadd(a, b); v[B + i + 4] = twk(csub(a, b), 2 * i, false);
        }
    #pragma unroll
    for (int B = 0; B < 16; B += 4)
        #pragma unroll
        for (int i = 0; i < 2; i++) {
            float2 a = v[B + i], b = v[B + i + 2];
            v[B + i] = cadd(a, b); v[B + i + 2] = twk(csub(a, b), 4 * i, false);
        }
    #pragma unroll
    for (int B = 0; B < 16; B += 2) {
        float2 a = v[B], b = v[B + 1];
        v[B] = cadd(a, b); v[B + 1] = csub(a, b);
    }
}

// inverse DIT DFT16 with conj twiddles: slot q holds X[br4(q)], natural output
__device__ __forceinline__ void dft16_dit_conj(float2* v) {
    #pragma unroll
    for (int B = 0; B < 16; B += 2) {
        float2 a = v[B], b = v[B + 1];
        v[B] = cadd(a, b); v[B + 1] = csub(a, b);
    }
    #pragma unroll
    for (int B = 0; B < 16; B += 4)
        #pragma unroll
        for (int i = 0; i < 2; i++) {
            float2 a = v[B + i], b = twk(v[B + i + 2], 4 * i, true);
            v[B + i] = cadd(a, b); v[B + i + 2] = csub(a, b);
        }
    #pragma unroll
    for (int B = 0; B < 16; B += 8)
        #pragma unroll
        for (int i = 0; i < 4; i++) {
            float2 a = v[B + i], b = twk(v[B + i + 4], 2 * i, true);
            v[B + i] = cadd(a, b); v[B + i + 4] = csub(a, b);
        }
    #pragma unroll
    for (int i = 0; i < 8; i++) {
        float2 a = v[i], b = twk(v[i + 8], i, true);
        v[i] = cadd(a, b); v[i + 8] = csub(a, b);
    }
}

// middle forward pass (two-chain twiddles)
template <int SL>
__device__ __forceinline__ void fwd_pass(float2* S, int base, float2 wa) {
    float2 v[16];
    #pragma unroll
    for (int j = 0; j < 16; j++) v[j] = S[AP(base + (j << SL))];
    dft16_dif(v);
    float2 w2 = cmul(wa, wa);
    S[AP(base)] = v[br4c(0)];
    float2 eo = wa, ee = w2;
    S[AP(base + (1 << SL))] = cmul(v[br4c(1)], eo);
    #pragma unroll
    for (int r = 2; r < 16; r += 2) {
        S[AP(base + (r << SL))] = cmul(v[br4c(r)], ee);
        eo = cmul(eo, w2);
        S[AP(base + ((r + 1) << SL))] = cmul(v[br4c(r + 1)], eo);
        ee = cmul(ee, w2);
    }
}

// middle inverse pass (wac already conjugated, two-chain)
template <int SL>
__device__ __forceinline__ void inv_pass(float2* S, int base, float2 wac) {
    float2 v[16];
    float2 w2 = cmul(wac, wac);
    v[br4c(0)] = S[AP(base)];
    float2 eo = wac, ee = w2;
    v[br4c(1)] = cmul(S[AP(base + (1 << SL))], eo);
    #pragma unroll
    for (int r = 2; r < 16; r += 2) {
        v[br4c(r)] = cmul(S[AP(base + (r << SL))], ee);
        eo = cmul(eo, w2);
        v[br4c(r + 1)] = cmul(S[AP(base + ((r + 1) << SL))], eo);
        ee = cmul(ee, w2);
    }
    dft16_dit_conj(v);
    #pragma unroll
    for (int j = 0; j < 16; j++) S[AP(base + (j << SL))] = v[j];
}

// ---------------- kernel 0: twiddle table ----------------
__global__ void tw_init_kernel() {
    int k = threadIdx.x;
    float s, c;
    sincospif(-(float)k / 4096.0f, &s, &c);
    g_tw[k] = make_float2(c, s);
}

// ---------------- kernel 1: embedding -> g_x packed (D,L) ----------------
__global__ void __launch_bounds__(1024) embed_kernel(const int* __restrict__ ids,
                                                     const float* __restrict__ emb,
                                                     const float* __restrict__ pos) {
    __shared__ float t0[32][33], t1[32][33];
    int l = blockIdx.x * 32 + threadIdx.y;
    int d = blockIdx.y * 32 + threadIdx.x;
    float v0 = 0.f, v1 = 0.f;
    if (l < LSEQ) {
        int id0 = ids[l], id1 = ids[LSEQ + l];
        float p = pos[(size_t)l * DMODEL + d];
        v0 = emb[(size_t)id0 * DMODEL + d] + p;
        v1 = emb[(size_t)id1 * DMODEL + d] + p;
    }
    t0[threadIdx.y][threadIdx.x] = v0;
    t1[threadIdx.y][threadIdx.x] = v1;
    __syncthreads();
    int l2 = blockIdx.x * 32 + threadIdx.x;
    int d2 = blockIdx.y * 32 + threadIdx.y;
    if (l2 < LSEQ)
        g_x[(size_t)d2 * LSEQ + l2] = make_float2(t0[threadIdx.x][threadIdx.y],
                                                  t1[threadIdx.x][threadIdx.y]);
}

// ---------------- kernel 2: filter spectra (fp16, conv-coalesced, pre-conjugated) ----
__global__ void __launch_bounds__(TTHR, 2) wspec_kernel(const float* __restrict__ filt_w) {
    extern __shared__ float2 S[];
    const int t = threadIdx.x;
    const int layer = blockIdx.x / (DMODEL / 2);
    const int d0 = (blockIdx.x % (DMODEL / 2)) * 2;
    const float* w0p = filt_w + ((size_t)layer * DMODEL + d0) * LSEQ;
    const float* w1p = w0p + LSEQ;

    // pass A: global -> regs -> smem
    {
        float2 v[16];
        #pragma unroll
        for (int j = 0; j < 16; j++) {
            int n = (j << 9) + t;
            v[j] = (n < LSEQ) ? make_float2(w0p[n], w1p[n]) : make_float2(0.f, 0.f);
        }
        dft16_dif(v);
        float2 wa = g_tw[t];
        float2 w2 = cmul(wa, wa);
        S[AP(t)] = v[br4c(0)];
        float2 eo = wa, ee = w2;
        S[AP((1 << 9) + t)] = cmul(v[br4c(1)], eo);
        #pragma unroll
        for (int r = 2; r < 16; r += 2) {
            S[AP((r << 9) + t)] = cmul(v[br4c(r)], ee);
            eo = cmul(eo, w2);
            S[AP(((r + 1) << 9) + t)] = cmul(v[br4c(r + 1)], eo);
            ee = cmul(ee, w2);
        }
    }
    __syncthreads();
    const int ra = t >> 5, vv = t & 31;
    fwd_pass<5>(S, (ra << 9) + vv, g_tw[vv << 4]);
    __syncthreads();
    const int rb = (t >> 1) & 15, w = t & 1;
    fwd_pass<1>(S, (ra << 9) + (rb << 5) + w, w ? g_tw[256] : make_float2(1.f, 0.f));
    __syncthreads();
    // final radix-2 (adjacent pairs)
    #pragma unroll
    for (int i = 0; i < 8; i++) {
        int p = (t << 4) + 2 * i;
        float2 a = S[AP(p)], b = S[AP(p + 1)];
        S[AP(p)] = cadd(a, b); S[AP(p + 1)] = csub(a, b);
    }
    __syncthreads();
    // unpack packed-real spectra, store fp16 conjugates in conv-coalesced order
    uint2* out0 = g_w + (((size_t)(layer * DMODEL + d0)) << 12);
    uint2* out1 = out0 + 4096;
    #pragma unroll
    for (int it = 0; it < 8; it++) {
        int pi = t + (it << 9);                // pair index, p = 2*pi
        int p = pi << 1;
        int k0 = (p >> 9) | (((p >> 5) & 15) << 4) | (((p >> 1) & 15) << 8);  // psd=0
        int k1 = k0 | 4096;
        int kn0 = (NFFT - k0) & (NFFT - 1);
        int kn1 = (NFFT - k1) & (NFFT - 1);
        int pn0 = ((kn0 & 15) << 9) | (((kn0 >> 4) & 15) << 5) | (((kn0 >> 8) & 15) << 1) | (kn0 >> 12);
        int pn1 = ((kn1 & 15) << 9) | (((kn1 >> 4) & 15) << 5) | (((kn1 >> 8) & 15) << 1) | (kn1 >> 12);
        float2 Zk0 = S[AP(p)],     Zn0 = S[AP(pn0)];
        float2 Zk1 = S[AP(p + 1)], Zn1 = S[AP(pn1)];
        float2 c00 = make_float2(0.5f * (Zk0.x + Zn0.x), 0.5f * (Zn0.y - Zk0.y));
        float2 c01 = make_float2(0.5f * (Zk1.x + Zn1.x), 0.5f * (Zn1.y - Zk1.y));
        float2 c10 = make_float2(0.5f * (Zk0.y + Zn0.y), 0.5f * (Zk0.x - Zn0.x));
        float2 c11 = make_float2(0.5f * (Zk1.y + Zn1.y), 0.5f * (Zk1.x - Zn1.x));
        int q = (pi & ~255) | ((pi & 15) << 4) | ((pi >> 4) & 15);
        out0[q] = make_uint2(f2h2(c00), f2h2(c01));
        out1[q] = make_uint2(f2h2(c10), f2h2(c11));
    }
}

// ---------------- kernel 3: ALL 12 layers, x resident in smem ----------------
__global__ void __launch_bounds__(TTHR, 2) conv_all_kernel(const float* __restrict__ filt_b) {
    extern __shared__ float2 sh[];
    float2* S = sh;
    float2* X = sh + SPAD;
    const int t = threadIdx.x;
    const int d = blockIdx.x;
    const int ra = t >> 5, vv = t & 31;
    const int rb = (t >> 1) & 15, w = t & 1;
    const int baseB = (ra << 9) + vv;
    const int baseC = (ra << 9) + (rb << 5) + w;

    const float2 waA = g_tw[t];
    const float2 waB = g_tw[vv << 4];
    const float2 waC = w ? g_tw[256] : make_float2(1.f, 0.f);

    float2* xg = g_x + (size_t)d * LSEQ;
    #pragma unroll
    for (int j = 0; j < 8; j++) {
        int n = (j << 9) + t;
        if (n < LSEQ) X[n] = xg[n];
    }
    __syncthreads();

    for (int layer = 0; layer < NLAYERS; layer++) {
        const uint2* wp = g_w + (((size_t)(layer * DMODEL + d)) << 12) + (ra << 8) + rb;
        const float bias = filt_b[layer * DMODEL + d];

        // pass A: X(smem) -> regs -> S
        {
            float2 v[16];
            #pragma unroll
            for (int j = 0; j < 16; j++) {
                int n = (j << 9) + t;
                v[j] = (n < LSEQ) ? X[n] : make_float2(0.f, 0.f);
            }
            dft16_dif(v);
            float2 w2 = cmul(waA, waA);
            S[AP(t)] = v[br4c(0)];
            float2 eo = waA, ee = w2;
            S[AP((1 << 9) + t)] = cmul(v[br4c(1)], eo);
            #pragma unroll
            for (int r = 2; r < 16; r += 2) {
                S[AP((r << 9) + t)] = cmul(v[br4c(r)], ee);
                eo = cmul(eo, w2);
                S[AP(((r + 1) << 9) + t)] = cmul(v[br4c(r + 1)], eo);
                ee = cmul(ee, w2);
            }
        }
        __syncthreads();
        fwd_pass<5>(S, baseB, waB);
        __syncthreads();
        // fused: pass C + radix-2 + spectrum multiply + inverse radix-2 + pass C'
        {
            float2 v[16];
            #pragma unroll
            for (int j = 0; j < 16; j++) v[j] = S[AP(baseC + (j << 1))];
            dft16_dif(v);
            float2 w2 = cmul(waC, waC);
            float2 fe = make_float2(1.f, 0.f);   // twiddle for even r (r=0 -> 1)
            float2 fo = waC;                     // twiddle for odd r
            #pragma unroll
            for (int r = 0; r < 16; r++) {
                const int s = br4c(r);
                float2 tw = (r & 1) ? fo : fe;
                float2 val = (r == 0) ? v[s] : cmul(v[s], tw);
                float2 oth;
                oth.x = __shfl_xor_sync(0xFFFFFFFFu, val.x, 1);
                oth.y = __shfl_xor_sync(0xFFFFFFFFu, val.y, 1);
                float2 a = w ? oth : val;
                float2 b = w ? val : oth;
                uint2 Wp = wp[r << 4];
                float2 W0 = h2f2(Wp.x);
                float2 W1 = h2f2(Wp.y);
                float2 ev = cmul(cadd(a, b), W0);
                float2 ov = cmul(csub(a, b), W1);
                float2 res = w ? csub(ev, ov) : cadd(ev, ov);
                v[s] = (r == 0) ? res : cmul(res, conjf(tw));
                if (r & 1) fo = cmul(fo, w2); else fe = cmul(fe, w2);
            }
            dft16_dit_conj(v);
            #pragma unroll
            for (int j = 0; j < 16; j++) S[AP(baseC + (j << 1))] = v[j];
        }
        __syncthreads();
        inv_pass<5>(S, baseB, conjf(waB));
        __syncthreads();
        // pass A': S -> regs -> residual update of X
        {
            float2 v[16];
            float2 wac = conjf(waA);
            float2 w2 = cmul(wac, wac);
            v[br4c(0)] = S[AP(t)];
            float2 eo = wac, ee = w2;
            v[br4c(1)] = cmul(S[AP((1 << 9) + t)], eo);
            #pragma unroll
            for (int r = 2; r < 16; r += 2) {
                v[br4c(r)] = cmul(S[AP((r << 9) + t)], ee);
                eo = cmul(eo, w2);
                v[br4c(r + 1)] = cmul(S[AP(((r + 1) << 9) + t)], eo);
                ee = cmul(ee, w2);
            }
            dft16_dit_conj(v);
            const float inv = 1.0f / (float)NFFT;
            #pragma unroll
            for (int j = 0; j < 16; j++) {
                int n = (j << 9) + t;
                int to = (n + 2047) & (NFFT - 1);
                if (to < LSEQ) {
                    float2 old = X[to];
                    X[to] = make_float2(old.x + v[j].x * inv + bias,
                                        old.y + v[j].y * inv + bias);
                }
            }
        }
        __syncthreads();
    }

    #pragma unroll
    for (int j = 0; j < 8; j++) {
        int n = (j << 9) + t;
        if (n < LSEQ) xg[n] = X[n];
    }
}

// ---------------- kernel 4: LayerNorm + projection ----------------
__global__ void __launch_bounds__(1024) final_kernel(const float* __restrict__ ln_g,
                                                     const float* __restrict__ ln_b,
                                                     const float* __restrict__ qa_w,
                                                     const float* __restrict__ qa_b,
                                                     float* __restrict__ out) {
    __shared__ float red[8][32][32];
    const int b  = blockIdx.y;
    const int tx = threadIdx.x, ty = threadIdx.y;
    const int l  = blockIdx.x * 32 + tx;
    const bool valid = (l < LSEQ);

    float S = 0, S2 = 0, A0 = 0, A1 = 0, G0 = 0, G1 = 0, B0 = 0, B1 = 0;
    for (int d = ty; d < DMODEL; d += 32) {
        float2 xv = valid ? g_x[(size_t)d * LSEQ + l] : make_float2(0.f, 0.f);
        float v  = b ? xv.y : xv.x;
        float g  = ln_g[d], bb = ln_b[d];
        float w0 = qa_w[2 * d], w1 = qa_w[2 * d + 1];
        S += v; S2 += v * v;
        float gv = g * v;
        A0 += gv * w0; A1 += gv * w1;
        G0 += g * w0;  G1 += g * w1;
        B0 += bb * w0; B1 += bb * w1;
    }
    red[0][ty][tx] = S;  red[1][ty][tx] = S2;
    red[2][ty][tx] = A0; red[3][ty][tx] = A1;
    red[4][ty][tx] = G0; red[5][ty][tx] = G1;
    red[6][ty][tx] = B0; red[7][ty][tx] = B1;
    __syncthreads();
    for (int s = 16; s > 0; s >>= 1) {
        if (ty < s) {
            #pragma unroll
            for (int a = 0; a < 8; a++) red[a][ty][tx] += red[a][ty + s][tx];
        }
        __syncthreads();
    }
    if (ty == 0 && valid) {
        float Sv = red[0][0][tx], S2v = red[1][0][tx];
        float a0 = red[2][0][tx], a1  = red[3][0][tx];
        float g0 = red[4][0][tx], g1  = red[5][0][tx];
        float b0 = red[6][0][tx], b1  = red[7][0][tx];
        float m   = Sv * (1.0f / DMODEL);
        float var = S2v * (1.0f / DMODEL) - m * m;
        float r   = rsqrtf(var + 1e-5f);
        float o0  = r * (a0 - m * g0) + b0 + qa_b[0];
        float o1  = r * (a1 - m * g1) + b1 + qa_b[1];
        out[b * LSEQ + l]            = o0;
        out[2 * LSEQ + b * LSEQ + l] = o1;
    }
}

// ---------------- host launcher ----------------
extern "C" void kernel_launch(void* const* d_in, const int* in_sizes, int n_in,
                              void* d_out, int out_size) {
    const int*   ids  = (const int*)  d_in[0];
    const float* emb  = (const float*)d_in[1];
    const float* pos  = (const float*)d_in[2];
    const float* fw   = (const float*)d_in[3];
    const float* fb   = (const float*)d_in[4];
    const float* lng  = (const float*)d_in[5];
    const float* lnb  = (const float*)d_in[6];
    const float* qaw  = (const float*)d_in[7];
    const float* qab  = (const float*)d_in[8];
    float* out = (float*)d_out;

    cudaFuncSetAttribute(wspec_kernel,    cudaFuncAttributeMaxDynamicSharedMemorySize, WSPEC_SMEM);
    cudaFuncSetAttribute(conv_all_kernel, cudaFuncAttributeMaxDynamicSharedMemorySize, CONV_SMEM);

    tw_init_kernel<<<1, 512>>>();
    embed_kernel<<<dim3(128, DMODEL / 32), dim3(32, 32)>>>(ids, emb, pos);
    wspec_kernel<<<NLAYERS * (DMODEL / 2), TTHR, WSPEC_SMEM>>>(fw);
    conv_all_kernel<<<DMODEL, TTHR, CONV_SMEM>>>(fb);
    final_kernel<<<dim3(128, 2), dim3(32, 32)>>>(lng, lnb, qaw, qab, out);
}

// round 4
// speedup vs baseline: 1.2355x; 1.2355x over previous
#include <cuda_runtime.h>
#include <cuda_fp16.h>
#include <math.h>

#define NFFT    8192
#define LSEQ    4095
#define DMODEL  768
#define NLAYERS 12
#define TTHR    512
#define SPAD    8448                      // 8192 + 8192/32 padding
#define AP(p)   ((p) + ((p) >> 5))
#define CONV_SMEM  ((SPAD + 4096) * sizeof(float2))
#define WSPEC_SMEM (SPAD * sizeof(float2))

// ---------------- device scratch ----------------
__device__ float2 g_x[DMODEL * LSEQ];                          // packed {b0,b1}, (D,L)
__device__ unsigned g_w[(size_t)NLAYERS * DMODEL * NFFT];      // fp16 spectra (half2 per bin), perm order, 302 MB
__device__ float2 g_tw[512];                                   // W_8192^k

// ---------------- complex helpers ----------------
__device__ __forceinline__ float2 cadd(float2 a, float2 b) { return make_float2(a.x + b.x, a.y + b.y); }
__device__ __forceinline__ float2 csub(float2 a, float2 b) { return make_float2(a.x - b.x, a.y - b.y); }
__device__ __forceinline__ float2 cmul(float2 a, float2 b) {
    return make_float2(fmaf(a.x, b.x, -a.y * b.y), fmaf(a.x, b.y, a.y * b.x));
}
__device__ __forceinline__ float2 cmulf(float2 a, float c, float s) {
    return make_float2(fmaf(a.x, c, -a.y * s), fmaf(a.x, s, a.y * c));
}
__device__ __forceinline__ float2 conjf(float2 a) { return make_float2(a.x, -a.y); }
__device__ __forceinline__ float2 h2f2(unsigned u) {
    __half2 h = *reinterpret_cast<__half2*>(&u);
    return __half22float2(h);
}
__device__ __forceinline__ unsigned f2h2(float2 v) {
    __half2 h = __floats2half2_rn(v.x, v.y);
    return *reinterpret_cast<unsigned*>(&h);
}

// 4-bit bit reversal (involution)
__device__ __forceinline__ constexpr int br4c(int r) {
    return ((r & 1) << 3) | ((r & 2) << 1) | ((r & 4) >> 1) | ((r & 8) >> 3);
}

// multiply by W16^k (forward) or conj (inverse)
__device__ __forceinline__ float2 twk(float2 a, int k, bool cj) {
    const float c1 = 0.92387953251128675613f;
    const float s1 = 0.38268343236508977173f;
    const float r2 = 0.70710678118654752440f;
    float c, s;
    switch (k & 7) {
        case 0: return a;
        case 1: c =  c1; s = -s1; break;
        case 2: c =  r2; s = -r2; break;
        case 3: c =  s1; s = -c1; break;
        case 4: return cj ? make_float2(-a.y, a.x) : make_float2(a.y, -a.x);
        case 5: c = -s1; s = -c1; break;
        case 6: c = -r2; s = -r2; break;
        default: c = -c1; s = -s1; break;
    }
    if (cj) s = -s;
    return cmulf(a, c, s);
}

// forward DIF DFT16: natural input, slot q holds X[br4(q)]
__device__ __forceinline__ void dft16_dif(float2* v) {
    #pragma unroll
    for (int i = 0; i < 8; i++) {
        float2 a = v[i], b = v[i + 8];
        v[i] = cadd(a, b); v[i + 8] = twk(csub(a, b), i, false);
    }
    #pragma unroll
    for (int B = 0; B < 16; B += 8)
        #pragma unroll
        for (int i = 0; i < 4; i++) {
            float2 a = v[B + i], b = v[B + i + 4];
            v[B + i] = cadd(a, b); v[B + i + 4] = twk(csub(a, b), 2 * i, false);
        }
    #pragma unroll
    for (int B = 0; B < 16; B += 4)
        #pragma unroll
        for (int i = 0; i < 2; i++) {
            float2 a = v[B + i], b = v[B + i + 2];
            v[B + i] = cadd(a, b); v[B + i + 2] = twk(csub(a, b), 4 * i, false);
        }
    #pragma unroll
    for (int B = 0; B < 16; B += 2) {
        float2 a = v[B], b = v[B + 1];
        v[B] = cadd(a, b); v[B + 1] = csub(a, b);
    }
}

// inverse DIT DFT16 with conj twiddles
__device__ __forceinline__ void dft16_dit_conj(float2* v) {
    #pragma unroll
    for (int B = 0; B < 16; B += 2) {
        float2 a = v[B], b = v[B + 1];
        v[B] = cadd(a, b); v[B + 1] = csub(a, b);
    }
    #pragma unroll
    for (int B = 0; B < 16; B += 4)
        #pragma unroll
        for (int i = 0; i < 2; i++) {
            float2 a = v[B + i], b = twk(v[B + i + 2], 4 * i, true);
            v[B + i] = cadd(a, b); v[B + i + 2] = csub(a, b);
        }
    #pragma unroll
    for (int B = 0; B < 16; B += 8)
        #pragma unroll
        for (int i = 0; i < 4; i++) {
            float2 a = v[B + i], b = twk(v[B + i + 4], 2 * i, true);
            v[B + i] = cadd(a, b); v[B + i + 4] = csub(a, b);
        }
    #pragma unroll
    for (int i = 0; i < 8; i++) {
        float2 a = v[i], b = twk(v[i + 8], i, true);
        v[i] = cadd(a, b); v[i + 8] = csub(a, b);
    }
}

// middle forward pass (two-chain twiddles)
template <int SL>
__device__ __forceinline__ void fwd_pass(float2* S, int base, float2 wa) {
    float2 v[16];
    #pragma unroll
    for (int j = 0; j < 16; j++) v[j] = S[AP(base + (j << SL))];
    dft16_dif(v);
    float2 w2 = cmul(wa, wa);
    S[AP(base)] = v[br4c(0)];
    float2 eo = wa, ee = w2;
    S[AP(base + (1 << SL))] = cmul(v[br4c(1)], eo);
    #pragma unroll
    for (int r = 2; r < 16; r += 2) {
        S[AP(base + (r << SL))] = cmul(v[br4c(r)], ee);
        eo = cmul(eo, w2);
        S[AP(base + ((r + 1) << SL))] = cmul(v[br4c(r + 1)], eo);
        ee = cmul(ee, w2);
    }
}

// middle inverse pass (wac already conjugated, two-chain)
template <int SL>
__device__ __forceinline__ void inv_pass(float2* S, int base, float2 wac) {
    float2 v[16];
    float2 w2 = cmul(wac, wac);
    v[br4c(0)] = S[AP(base)];
    float2 eo = wac, ee = w2;
    v[br4c(1)] = cmul(S[AP(base + (1 << SL))], eo);
    #pragma unroll
    for (int r = 2; r < 16; r += 2) {
        v[br4c(r)] = cmul(S[AP(base + (r << SL))], ee);
        eo = cmul(eo, w2);
        v[br4c(r + 1)] = cmul(S[AP(base + ((r + 1) << SL))], eo);
        ee = cmul(ee, w2);
    }
    dft16_dit_conj(v);
    #pragma unroll
    for (int j = 0; j < 16; j++) S[AP(base + (j << SL))] = v[j];
}

// ---------------- kernel 0: twiddle table ----------------
__global__ void tw_init_kernel() {
    int k = threadIdx.x;
    float s, c;
    sincospif(-(float)k / 4096.0f, &s, &c);
    g_tw[k] = make_float2(c, s);
}

// ---------------- kernel 1: embedding -> g_x packed (D,L) ----------------
__global__ void __launch_bounds__(1024) embed_kernel(const int* __restrict__ ids,
                                                     const float* __restrict__ emb,
                                                     const float* __restrict__ pos) {
    __shared__ float t0[32][33], t1[32][33];
    int l = blockIdx.x * 32 + threadIdx.y;
    int d = blockIdx.y * 32 + threadIdx.x;
    float v0 = 0.f, v1 = 0.f;
    if (l < LSEQ) {
        int id0 = ids[l], id1 = ids[LSEQ + l];
        float p = pos[(size_t)l * DMODEL + d];
        v0 = emb[(size_t)id0 * DMODEL + d] + p;
        v1 = emb[(size_t)id1 * DMODEL + d] + p;
    }
    t0[threadIdx.y][threadIdx.x] = v0;
    t1[threadIdx.y][threadIdx.x] = v1;
    __syncthreads();
    int l2 = blockIdx.x * 32 + threadIdx.x;
    int d2 = blockIdx.y * 32 + threadIdx.y;
    if (l2 < LSEQ)
        g_x[(size_t)d2 * LSEQ + l2] = make_float2(t0[threadIdx.x][threadIdx.y],
                                                  t1[threadIdx.x][threadIdx.y]);
}

// ---------------- kernel 2: filter spectra (fp16, perm order, pre-conjugated) -------
__global__ void __launch_bounds__(TTHR, 2) wspec_kernel(const float* __restrict__ filt_w) {
    extern __shared__ float2 S[];
    const int t = threadIdx.x;
    const int layer = blockIdx.x / (DMODEL / 2);
    const int d0 = (blockIdx.x % (DMODEL / 2)) * 2;
    const float* w0p = filt_w + ((size_t)layer * DMODEL + d0) * LSEQ;
    const float* w1p = w0p + LSEQ;

    // pass A: global -> regs -> smem
    {
        float2 v[16];
        #pragma unroll
        for (int j = 0; j < 16; j++) {
            int n = (j << 9) + t;
            v[j] = (n < LSEQ) ? make_float2(w0p[n], w1p[n]) : make_float2(0.f, 0.f);
        }
        dft16_dif(v);
        float2 wa = g_tw[t];
        float2 w2 = cmul(wa, wa);
        S[AP(t)] = v[br4c(0)];
        float2 eo = wa, ee = w2;
        S[AP((1 << 9) + t)] = cmul(v[br4c(1)], eo);
        #pragma unroll
        for (int r = 2; r < 16; r += 2) {
            S[AP((r << 9) + t)] = cmul(v[br4c(r)], ee);
            eo = cmul(eo, w2);
            S[AP(((r + 1) << 9) + t)] = cmul(v[br4c(r + 1)], eo);
            ee = cmul(ee, w2);
        }
    }
    __syncthreads();
    const int ra = t >> 5, vv = t & 31;
    fwd_pass<5>(S, (ra << 9) + vv, g_tw[vv << 4]);
    __syncthreads();
    const int rb = (t >> 1) & 15, w = t & 1;
    fwd_pass<1>(S, (ra << 9) + (rb << 5) + w, w ? g_tw[256] : make_float2(1.f, 0.f));
    __syncthreads();
    // final radix-2 (adjacent pairs)
    #pragma unroll
    for (int i = 0; i < 8; i++) {
        int p = (t << 4) + 2 * i;
        float2 a = S[AP(p)], b = S[AP(p + 1)];
        S[AP(p)] = cadd(a, b); S[AP(p + 1)] = csub(a, b);
    }
    __syncthreads();
    // unpack packed-real spectra, store fp16 conjugates in perm order (coalesced)
    unsigned* out0 = g_w + ((size_t)(layer * DMODEL + d0)) * NFFT;
    unsigned* out1 = out0 + NFFT;
    #pragma unroll
    for (int it = 0; it < 16; it++) {
        int p = t + (it << 9);
        int pra = p >> 9, prb = (p >> 5) & 15, prc = (p >> 1) & 15, psd = p & 1;
        int k = pra | (prb << 4) | (prc << 8) | (psd << 12);
        int kn = (NFFT - k) & (NFFT - 1);
        int pn = ((kn & 15) << 9) | (((kn >> 4) & 15) << 5) | (((kn >> 8) & 15) << 1) | (kn >> 12);
        float2 Zk = S[AP(p)], Zn = S[AP(pn)];
        out0[p] = f2h2(make_float2(0.5f * (Zk.x + Zn.x), 0.5f * (Zn.y - Zk.y)));
        out1[p] = f2h2(make_float2(0.5f * (Zk.y + Zn.y), 0.5f * (Zk.x - Zn.x)));
    }
}

// ---------------- kernel 3: ALL 12 layers, R2 phase structure, X resident ----------
__global__ void __launch_bounds__(TTHR, 2) conv_all_kernel(const float* __restrict__ filt_b) {
    extern __shared__ float2 sh[];
    float2* S = sh;
    float2* X = sh + SPAD;
    const int t = threadIdx.x;
    const int d = blockIdx.x;
    const int ra = t >> 5, vv = t & 31;
    const int rb = (t >> 1) & 15, w = t & 1;
    const int baseB = (ra << 9) + vv;
    const int baseC = (ra << 9) + (rb << 5) + w;

    const float2 waA = g_tw[t];
    const float2 waB = g_tw[vv << 4];
    const float2 waC = w ? g_tw[256] : make_float2(1.f, 0.f);

    float2* xg = g_x + (size_t)d * LSEQ;
    #pragma unroll
    for (int j = 0; j < 8; j++) {
        int n = (j << 9) + t;
        if (n < LSEQ) X[n] = xg[n];
    }
    __syncthreads();

    for (int layer = 0; layer < NLAYERS; layer++) {
        const float bias = filt_b[layer * DMODEL + d];

        // pass A: X(smem) -> regs -> S
        {
            float2 v[16];
            #pragma unroll
            for (int j = 0; j < 16; j++) {
                int n = (j << 9) + t;
                v[j] = (n < LSEQ) ? X[n] : make_float2(0.f, 0.f);
            }
            dft16_dif(v);
            float2 w2 = cmul(waA, waA);
            S[AP(t)] = v[br4c(0)];
            float2 eo = waA, ee = w2;
            S[AP((1 << 9) + t)] = cmul(v[br4c(1)], eo);
            #pragma unroll
            for (int r = 2; r < 16; r += 2) {
                S[AP((r << 9) + t)] = cmul(v[br4c(r)], ee);
                eo = cmul(eo, w2);
                S[AP(((r + 1) << 9) + t)] = cmul(v[br4c(r + 1)], eo);
                ee = cmul(ee, w2);
            }
        }
        __syncthreads();
        fwd_pass<5>(S, baseB, waB);
        __syncthreads();
        fwd_pass<1>(S, baseC, waC);
        __syncthreads();
        // pass D: radix-2 fwd + fp16 spectrum multiply + radix-2 inv (smem pairs)
        {
            const uint2* wp = (const uint2*)(g_w + ((size_t)(layer * DMODEL + d)) * NFFT + ((size_t)t << 4));
            #pragma unroll
            for (int i = 0; i < 8; i++) {
                int p = (t << 4) + 2 * i;
                float2 a = S[AP(p)], b = S[AP(p + 1)];
                uint2 Wp = wp[i];
                float2 e = cmul(cadd(a, b), h2f2(Wp.x));
                float2 o = cmul(csub(a, b), h2f2(Wp.y));
                S[AP(p)]     = cadd(e, o);
                S[AP(p + 1)] = csub(e, o);
            }
        }
        __syncthreads();
        inv_pass<1>(S, baseC, conjf(waC));
        __syncthreads();
        inv_pass<5>(S, baseB, conjf(waB));
        __syncthreads();
        // pass A': S -> regs -> residual update of X
        {
            float2 v[16];
            float2 wac = conjf(waA);
            float2 w2 = cmul(wac, wac);
            v[br4c(0)] = S[AP(t)];
            float2 eo = wac, ee = w2;
            v[br4c(1)] = cmul(S[AP((1 << 9) + t)], eo);
            #pragma unroll
            for (int r = 2; r < 16; r += 2) {
                v[br4c(r)] = cmul(S[AP((r << 9) + t)], ee);
                eo = cmul(eo, w2);
                v[br4c(r + 1)] = cmul(S[AP(((r + 1) << 9) + t)], eo);
                ee = cmul(ee, w2);
            }
            dft16_dit_conj(v);
            const float inv = 1.0f / (float)NFFT;
            #pragma unroll
            for (int j = 0; j < 16; j++) {
                int n = (j << 9) + t;
                int to = (n + 2047) & (NFFT - 1);
                if (to < LSEQ) {
                    float2 old = X[to];
                    X[to] = make_float2(old.x + v[j].x * inv + bias,
                                        old.y + v[j].y * inv + bias);
                }
            }
        }
        __syncthreads();
    }

    #pragma unroll
    for (int j = 0; j < 8; j++) {
        int n = (j << 9) + t;
        if (n < LSEQ) xg[n] = X[n];
    }
}

// ---------------- kernel 4: LayerNorm + projection ----------------
__global__ void __launch_bounds__(1024) final_kernel(const float* __restrict__ ln_g,
                                                     const float* __restrict__ ln_b,
                                                     const float* __restrict__ qa_w,
                                                     const float* __restrict__ qa_b,
                                                     float* __restrict__ out) {
    __shared__ float red[8][32][32];
    const int b  = blockIdx.y;
    const int tx = threadIdx.x, ty = threadIdx.y;
    const int l  = blockIdx.x * 32 + tx;
    const bool valid = (l < LSEQ);

    float S = 0, S2 = 0, A0 = 0, A1 = 0, G0 = 0, G1 = 0, B0 = 0, B1 = 0;
    for (int d = ty; d < DMODEL; d += 32) {
        float2 xv = valid ? g_x[(size_t)d * LSEQ + l] : make_float2(0.f, 0.f);
        float v  = b ? xv.y : xv.x;
        float g  = ln_g[d], bb = ln_b[d];
        float w0 = qa_w[2 * d], w1 = qa_w[2 * d + 1];
        S += v; S2 += v * v;
        float gv = g * v;
        A0 += gv * w0; A1 += gv * w1;
        G0 += g * w0;  G1 += g * w1;
        B0 += bb * w0; B1 += bb * w1;
    }
    red[0][ty][tx] = S;  red[1][ty][tx] = S2;
    red[2][ty][tx] = A0; red[3][ty][tx] = A1;
    red[4][ty][tx] = G0; red[5][ty][tx] = G1;
    red[6][ty][tx] = B0; red[7][ty][tx] = B1;
    __syncthreads();
    for (int s = 16; s > 0; s >>= 1) {
        if (ty < s) {
            #pragma unroll
            for (int a = 0; a < 8; a++) red[a][ty][tx] += red[a][ty + s][tx];
        }
        __syncthreads();
    }
    if (ty == 0 && valid) {
        float Sv = red[0][0][tx], S2v = red[1][0][tx];
        float a0 = red[2][0][tx], a1  = red[3][0][tx];
        float g0 = red[4][0][tx], g1  = red[5][0][tx];
        float b0 = red[6][0][tx], b1  = red[7][0][tx];
        float m   = Sv * (1.0f / DMODEL);
        float var = S2v * (1.0f / DMODEL) - m * m;
        float r   = rsqrtf(var + 1e-5f);
        float o0  = r * (a0 - m * g0) + b0 + qa_b[0];
        float o1  = r * (a1 - m * g1) + b1 + qa_b[1];
        out[b * LSEQ + l]            = o0;
        out[2 * LSEQ + b * LSEQ + l] = o1;
    }
}

// ---------------- host launcher ----------------
extern "C" void kernel_launch(void* const* d_in, const int* in_sizes, int n_in,
                              void* d_out, int out_size) {
    const int*   ids  = (const int*)  d_in[0];
    const float* emb  = (const float*)d_in[1];
    const float* pos  = (const float*)d_in[2];
    const float* fw   = (const float*)d_in[3];
    const float* fb   = (const float*)d_in[4];
    const float* lng  = (const float*)d_in[5];
    const float* lnb  = (const float*)d_in[6];
    const float* qaw  = (const float*)d_in[7];
    const float* qab  = (const float*)d_in[8];
    float* out = (float*)d_out;

    cudaFuncSetAttribute(wspec_kernel,    cudaFuncAttributeMaxDynamicSharedMemorySize, WSPEC_SMEM);
    cudaFuncSetAttribute(conv_all_kernel, cudaFuncAttributeMaxDynamicSharedMemorySize, CONV_SMEM);

    tw_init_kernel<<<1, 512>>>();
    embed_kernel<<<dim3(128, DMODEL / 32), dim3(32, 32)>>>(ids, emb, pos);
    wspec_kernel<<<NLAYERS * (DMODEL / 2), TTHR, WSPEC_SMEM>>>(fw);
    conv_all_kernel<<<DMODEL, TTHR, CONV_SMEM>>>(fb);
    final_kernel<<<dim3(128, 2), dim3(32, 32)>>>(lng, lnb, qaw, qab, out);
}

// round 5
// speedup vs baseline: 1.5102x; 1.2224x over previous
#include <cuda_runtime.h>
#include <cuda_fp16.h>
#include <math.h>

#define NFFT    8192
#define LSEQ    4095
#define DMODEL  768
#define NLAYERS 12
#define TTHR    512
#define SPAD    9216                      // 8192 + 2*(8192/16) padding
#define AP(p)   ((p) + (((p) >> 4) << 1))
#define CONV_SMEM  ((SPAD + 4096) * sizeof(float2))
#define WSPEC_SMEM (SPAD * sizeof(float2))

// ---------------- device scratch ----------------
__device__ float2 g_x[DMODEL * LSEQ];                      // packed {b0,b1}, (D,L)
__device__ uint4  g_w[(size_t)NLAYERS * DMODEL * 2048];    // fp16 spectra, perm order, 302 MB
__device__ float2 g_tw[512];                               // W_8192^k

// ---------------- complex helpers ----------------
__device__ __forceinline__ float2 cadd(float2 a, float2 b) { return make_float2(a.x + b.x, a.y + b.y); }
__device__ __forceinline__ float2 csub(float2 a, float2 b) { return make_float2(a.x - b.x, a.y - b.y); }
__device__ __forceinline__ float2 cmul(float2 a, float2 b) {
    return make_float2(fmaf(a.x, b.x, -a.y * b.y), fmaf(a.x, b.y, a.y * b.x));
}
__device__ __forceinline__ float2 cmulf(float2 a, float c, float s) {
    return make_float2(fmaf(a.x, c, -a.y * s), fmaf(a.x, s, a.y * c));
}
__device__ __forceinline__ float2 conjf(float2 a) { return make_float2(a.x, -a.y); }
__device__ __forceinline__ float2 h2f2(unsigned u) {
    __half2 h = *reinterpret_cast<__half2*>(&u);
    return __half22float2(h);
}
__device__ __forceinline__ unsigned f2h2(float2 v) {
    __half2 h = __floats2half2_rn(v.x, v.y);
    return *reinterpret_cast<unsigned*>(&h);
}

// 4-bit bit reversal (involution)
__device__ __forceinline__ constexpr int br4c(int r) {
    return ((r & 1) << 3) | ((r & 2) << 1) | ((r & 4) >> 1) | ((r & 8) >> 3);
}
__device__ __forceinline__ int br4(int r) {
    return ((r & 1) << 3) | ((r & 2) << 1) | ((r & 4) >> 1) | ((r & 8) >> 3);
}

// position <-> frequency maps for decomposition 16(512) x 16(32) x 2(16) x 16(1)
__device__ __forceinline__ int posk(int p) {   // position -> bin
    return (p >> 9) | (((p >> 5) & 15) << 4) | (((p >> 4) & 1) << 8) | (br4(p & 15) << 9);
}
__device__ __forceinline__ int kpos(int k) {   // bin -> position
    return ((k & 15) << 9) | (((k >> 4) & 15) << 5) | (((k >> 8) & 1) << 4) | br4((k >> 9) & 15);
}

// multiply by W16^k (forward) or conj (inverse)
__device__ __forceinline__ float2 twk(float2 a, int k, bool cj) {
    const float c1 = 0.92387953251128675613f;
    const float s1 = 0.38268343236508977173f;
    const float r2 = 0.70710678118654752440f;
    float c, s;
    switch (k & 7) {
        case 0: return a;
        case 1: c =  c1; s = -s1; break;
        case 2: c =  r2; s = -r2; break;
        case 3: c =  s1; s = -c1; break;
        case 4: return cj ? make_float2(-a.y, a.x) : make_float2(a.y, -a.x);
        case 5: c = -s1; s = -c1; break;
        case 6: c = -r2; s = -r2; break;
        default: c = -c1; s = -s1; break;
    }
    if (cj) s = -s;
    return cmulf(a, c, s);
}

// forward DIF DFT16: natural input, slot q holds bin br4(q)
__device__ __forceinline__ void dft16_dif(float2* v) {
    #pragma unroll
    for (int i = 0; i < 8; i++) {
        float2 a = v[i], b = v[i + 8];
        v[i] = cadd(a, b); v[i + 8] = twk(csub(a, b), i, false);
    }
    #pragma unroll
    for (int B = 0; B < 16; B += 8)
        #pragma unroll
        for (int i = 0; i < 4; i++) {
            float2 a = v[B + i], b = v[B + i + 4];
            v[B + i] = cadd(a, b); v[B + i + 4] = twk(csub(a, b), 2 * i, false);
        }
    #pragma unroll
    for (int B = 0; B < 16; B += 4)
        #pragma unroll
        for (int i = 0; i < 2; i++) {
            float2 a = v[B + i], b = v[B + i + 2];
            v[B + i] = cadd(a, b); v[B + i + 2] = twk(csub(a, b), 4 * i, false);
        }
    #pragma unroll
    for (int B = 0; B < 16; B += 2) {
        float2 a = v[B], b = v[B + 1];
        v[B] = cadd(a, b); v[B + 1] = csub(a, b);
    }
}

// inverse DIT DFT16 with conj twiddles: slot q holds bin br4(q), natural output
__device__ __forceinline__ void dft16_dit_conj(float2* v) {
    #pragma unroll
    for (int B = 0; B < 16; B += 2) {
        float2 a = v[B], b = v[B + 1];
        v[B] = cadd(a, b); v[B + 1] = csub(a, b);
    }
    #pragma unroll
    for (int B = 0; B < 16; B += 4)
        #pragma unroll
        for (int i = 0; i < 2; i++) {
            float2 a = v[B + i], b = twk(v[B + i + 2], 4 * i, true);
            v[B + i] = cadd(a, b); v[B + i + 2] = csub(a, b);
        }
    #pragma unroll
    for (int B = 0; B < 16; B += 8)
        #pragma unroll
        for (int i = 0; i < 4; i++) {
            float2 a = v[B + i], b = twk(v[B + i + 4], 2 * i, true);
            v[B + i] = cadd(a, b); v[B + i + 4] = csub(a, b);
        }
    #pragma unroll
    for (int i = 0; i < 8; i++) {
        float2 a = v[i], b = twk(v[i + 8], i, true);
        v[i] = cadd(a, b); v[i + 8] = csub(a, b);
    }
}

// apply forward twiddle chain in place (slot br4c(r) gets *wa^r), two chains
__device__ __forceinline__ void chain_fwd(float2* v, float2 wa) {
    float2 w2 = cmul(wa, wa);
    float2 eo = wa, ee = w2;
    v[br4c(1)] = cmul(v[br4c(1)], eo);
    #pragma unroll
    for (int r = 2; r < 16; r += 2) {
        v[br4c(r)] = cmul(v[br4c(r)], ee);
        eo = cmul(eo, w2);
        v[br4c(r + 1)] = cmul(v[br4c(r + 1)], eo);
        ee = cmul(ee, w2);
    }
}

// pass B forward: radix-16 @32 with twiddle + fused radix-2 @16 via shfl
__device__ __forceinline__ void passB_fwd(float2* S, int baseB, float2 waB,
                                          bool lo, float2 w32) {
    float2 v[16];
    #pragma unroll
    for (int j = 0; j < 16; j++) v[j] = S[AP(baseB + (j << 5))];
    dft16_dif(v);
    chain_fwd(v, waB);
    #pragma unroll
    for (int q = 0; q < 16; q++) {
        float2 val = v[q], oth;
        oth.x = __shfl_xor_sync(0xFFFFFFFFu, val.x, 16);
        oth.y = __shfl_xor_sync(0xFFFFFFFFu, val.y, 16);
        float2 sum = cadd(val, oth);
        float2 dif = cmul(csub(oth, val), w32);
        v[q] = lo ? sum : dif;
    }
    #pragma unroll
    for (int r = 0; r < 16; r++) S[AP(baseB + (r << 5))] = v[br4c(r)];
}

// pass B inverse: undo radix-2 @16 (shfl, conj W32), conj twiddle, DIT-16 @32
__device__ __forceinline__ void passB_inv(float2* S, int baseB, float2 cwB,
                                          bool lo, float2 cw32) {
    float2 v[16];
    #pragma unroll
    for (int r = 0; r < 16; r++) v[br4c(r)] = S[AP(baseB + (r << 5))];
    #pragma unroll
    for (int q = 0; q < 16; q++) {
        float2 tmp = lo ? v[q] : cmul(v[q], cw32);
        float2 oth;
        oth.x = __shfl_xor_sync(0xFFFFFFFFu, tmp.x, 16);
        oth.y = __shfl_xor_sync(0xFFFFFFFFu, tmp.y, 16);
        v[q] = lo ? cadd(tmp, oth) : csub(oth, tmp);
    }
    chain_fwd(v, cwB);   // same chain structure, conj base gives conj powers
    dft16_dit_conj(v);
    #pragma unroll
    for (int j = 0; j < 16; j++) S[AP(baseB + (j << 5))] = v[j];
}

// ---------------- kernel 0: twiddle table ----------------
__global__ void tw_init_kernel() {
    int k = threadIdx.x;
    float s, c;
    sincospif(-(float)k / 4096.0f, &s, &c);
    g_tw[k] = make_float2(c, s);
}

// ---------------- kernel 1: embedding -> g_x packed (D,L) ----------------
__global__ void __launch_bounds__(1024) embed_kernel(const int* __restrict__ ids,
                                                     const float* __restrict__ emb,
                                                     const float* __restrict__ pos) {
    __shared__ float t0[32][33], t1[32][33];
    int l = blockIdx.x * 32 + threadIdx.y;
    int d = blockIdx.y * 32 + threadIdx.x;
    float v0 = 0.f, v1 = 0.f;
    if (l < LSEQ) {
        int id0 = ids[l], id1 = ids[LSEQ + l];
        float p = pos[(size_t)l * DMODEL + d];
        v0 = emb[(size_t)id0 * DMODEL + d] + p;
        v1 = emb[(size_t)id1 * DMODEL + d] + p;
    }
    t0[threadIdx.y][threadIdx.x] = v0;
    t1[threadIdx.y][threadIdx.x] = v1;
    __syncthreads();
    int l2 = blockIdx.x * 32 + threadIdx.x;
    int d2 = blockIdx.y * 32 + threadIdx.y;
    if (l2 < LSEQ)
        g_x[(size_t)d2 * LSEQ + l2] = make_float2(t0[threadIdx.x][threadIdx.y],
                                                  t1[threadIdx.x][threadIdx.y]);
}

// ---------------- kernel 2: filter spectra (fp16, new perm order, pre-conj) --------
__global__ void __launch_bounds__(TTHR, 2) wspec_kernel(const float* __restrict__ filt_w) {
    extern __shared__ float2 S[];
    const int t = threadIdx.x;
    const int layer = blockIdx.x / (DMODEL / 2);
    const int d0 = (blockIdx.x % (DMODEL / 2)) * 2;
    const int ra = t >> 5, vv = t & 31;
    const bool lo = vv < 16;
    const int baseB = (ra << 9) + vv;
    const float2 waB = g_tw[vv << 4];
    float s32, c32;
    sincospif(-(float)(vv & 15) / 16.0f, &s32, &c32);
    const float2 w32 = make_float2(c32, s32);

    const float* w0p = filt_w + ((size_t)layer * DMODEL + d0) * LSEQ;
    const float* w1p = w0p + LSEQ;

    // pass A: global -> regs -> smem
    {
        float2 v[16];
        #pragma unroll
        for (int j = 0; j < 16; j++) {
            int n = (j << 9) + t;
            v[j] = (n < LSEQ) ? make_float2(w0p[n], w1p[n]) : make_float2(0.f, 0.f);
        }
        dft16_dif(v);
        chain_fwd(v, g_tw[t]);
        #pragma unroll
        for (int r = 0; r < 16; r++) S[AP((r << 9) + t)] = v[br4c(r)];
    }
    __syncthreads();
    passB_fwd(S, baseB, waB, lo, w32);
    __syncthreads();
    // pass C: final DFT-16 over 16 consecutive, store in slot order
    {
        float4* Sv = reinterpret_cast<float4*>(S);
        const int f = 9 * t;
        float2 v[16];
        #pragma unroll
        for (int j = 0; j < 8; j++) {
            float4 q4 = Sv[f + j];
            v[2 * j]     = make_float2(q4.x, q4.y);
            v[2 * j + 1] = make_float2(q4.z, q4.w);
        }
        dft16_dif(v);
        #pragma unroll
        for (int j = 0; j < 8; j++)
            Sv[f + j] = make_float4(v[2 * j].x, v[2 * j].y, v[2 * j + 1].x, v[2 * j + 1].y);
    }
    __syncthreads();
    // unpack packed-real spectra, store fp16 conjugates at position index (coalesced)
    unsigned* out0 = reinterpret_cast<unsigned*>(g_w) + (size_t)(layer * DMODEL + d0) * NFFT;
    unsigned* out1 = out0 + NFFT;
    #pragma unroll
    for (int it = 0; it < 16; it++) {
        int p = t + (it << 9);
        int k = posk(p);
        int kn = (NFFT - k) & (NFFT - 1);
        int pn = kpos(kn);
        float2 Zk = S[AP(p)], Zn = S[AP(pn)];
        out0[p] = f2h2(make_float2(0.5f * (Zk.x + Zn.x), 0.5f * (Zn.y - Zk.y)));
        out1[p] = f2h2(make_float2(0.5f * (Zk.y + Zn.y), 0.5f * (Zk.x - Zn.x)));
    }
}

// ---------------- kernel 3: ALL 12 layers, 5-phase FFT, X resident ----------------
__global__ void __launch_bounds__(TTHR, 2) conv_all_kernel(const float* __restrict__ filt_b) {
    extern __shared__ float2 sh[];
    float2* S = sh;
    float2* X = sh + SPAD;
    const int t = threadIdx.x;
    const int d = blockIdx.x;
    const int ra = t >> 5, vv = t & 31;
    const bool lo = vv < 16;
    const int baseB = (ra << 9) + vv;
    const float2 waA = g_tw[t];
    const float2 cwA = conjf(waA);
    const float2 waB = g_tw[vv << 4];
    const float2 cwB = conjf(waB);
    float s32, c32;
    sincospif(-(float)(vv & 15) / 16.0f, &s32, &c32);
    const float2 w32  = make_float2(c32, s32);
    const float2 cw32 = make_float2(c32, -s32);

    float2* xg = g_x + (size_t)d * LSEQ;
    #pragma unroll
    for (int j = 0; j < 8; j++) {
        int n = (j << 9) + t;
        if (n < LSEQ) X[n] = xg[n];
    }
    __syncthreads();

    for (int layer = 0; layer < NLAYERS; layer++) {
        const float bias = filt_b[layer * DMODEL + d];

        // pass A: X(smem) -> regs -> S
        {
            float2 v[16];
            #pragma unroll
            for (int j = 0; j < 16; j++) {
                int n = (j << 9) + t;
                v[j] = (n < LSEQ) ? X[n] : make_float2(0.f, 0.f);
            }
            dft16_dif(v);
            chain_fwd(v, waA);
            #pragma unroll
            for (int r = 0; r < 16; r++) S[AP((r << 9) + t)] = v[br4c(r)];
        }
        __syncthreads();
        passB_fwd(S, baseB, waB, lo, w32);
        __syncthreads();
        // pass Cf: final DFT-16 + fp16 spectrum multiply + inverse DFT-16, registers only
        {
            const uint4* wrow = g_w + (((size_t)(layer * DMODEL + d)) << 11) + (t << 2);
            uint4 W0 = wrow[0], W1 = wrow[1], W2 = wrow[2], W3 = wrow[3];
            float4* Sv = reinterpret_cast<float4*>(S);
            const int f = 9 * t;
            float2 v[16];
            #pragma unroll
            for (int j = 0; j < 8; j++) {
                float4 q4 = Sv[f + j];
                v[2 * j]     = make_float2(q4.x, q4.y);
                v[2 * j + 1] = make_float2(q4.z, q4.w);
            }
            dft16_dif(v);
            v[0]  = cmul(v[0],  h2f2(W0.x)); v[1]  = cmul(v[1],  h2f2(W0.y));
            v[2]  = cmul(v[2],  h2f2(W0.z)); v[3]  = cmul(v[3],  h2f2(W0.w));
            v[4]  = cmul(v[4],  h2f2(W1.x)); v[5]  = cmul(v[5],  h2f2(W1.y));
            v[6]  = cmul(v[6],  h2f2(W1.z)); v[7]  = cmul(v[7],  h2f2(W1.w));
            v[8]  = cmul(v[8],  h2f2(W2.x)); v[9]  = cmul(v[9],  h2f2(W2.y));
            v[10] = cmul(v[10], h2f2(W2.z)); v[11] = cmul(v[11], h2f2(W2.w));
            v[12] = cmul(v[12], h2f2(W3.x)); v[13] = cmul(v[13], h2f2(W3.y));
            v[14] = cmul(v[14], h2f2(W3.z)); v[15] = cmul(v[15], h2f2(W3.w));
            dft16_dit_conj(v);
            #pragma unroll
            for (int j = 0; j < 8; j++)
                Sv[f + j] = make_float4(v[2 * j].x, v[2 * j].y, v[2 * j + 1].x, v[2 * j + 1].y);
        }
        __syncthreads();
        passB_inv(S, baseB, cwB, lo, cw32);
        __syncthreads();
        // pass A': S -> regs -> residual update of X
        {
            float2 v[16];
            #pragma unroll
            for (int r = 0; r < 16; r++) v[br4c(r)] = S[AP((r << 9) + t)];
            chain_fwd(v, cwA);
            dft16_dit_conj(v);
            const float inv = 1.0f / (float)NFFT;
            #pragma unroll
            for (int j = 0; j < 16; j++) {
                int n = (j << 9) + t;
                int to = (n + 2047) & (NFFT - 1);
                if (to < LSEQ) {
                    float2 old = X[to];
                    X[to] = make_float2(old.x + v[j].x * inv + bias,
                                        old.y + v[j].y * inv + bias);
                }
            }
        }
        __syncthreads();
    }

    #pragma unroll
    for (int j = 0; j < 8; j++) {
        int n = (j << 9) + t;
        if (n < LSEQ) xg[n] = X[n];
    }
}

// ---------------- kernel 4: LayerNorm + projection ----------------
__global__ void __launch_bounds__(1024) final_kernel(const float* __restrict__ ln_g,
                                                     const float* __restrict__ ln_b,
                                                     const float* __restrict__ qa_w,
                                                     const float* __restrict__ qa_b,
                                                     float* __restrict__ out) {
    __shared__ float red[8][32][32];
    const int b  = blockIdx.y;
    const int tx = threadIdx.x, ty = threadIdx.y;
    const int l  = blockIdx.x * 32 + tx;
    const bool valid = (l < LSEQ);

    float S = 0, S2 = 0, A0 = 0, A1 = 0, G0 = 0, G1 = 0, B0 = 0, B1 = 0;
    for (int d = ty; d < DMODEL; d += 32) {
        float2 xv = valid ? g_x[(size_t)d * LSEQ + l] : make_float2(0.f, 0.f);
        float v  = b ? xv.y : xv.x;
        float g  = ln_g[d], bb = ln_b[d];
        float w0 = qa_w[2 * d], w1 = qa_w[2 * d + 1];
        S += v; S2 += v * v;
        float gv = g * v;
        A0 += gv * w0; A1 += gv * w1;
        G0 += g * w0;  G1 += g * w1;
        B0 += bb * w0; B1 += bb * w1;
    }
    red[0][ty][tx] = S;  red[1][ty][tx] = S2;
    red[2][ty][tx] = A0; red[3][ty][tx] = A1;
    red[4][ty][tx] = G0; red[5][ty][tx] = G1;
    red[6][ty][tx] = B0; red[7][ty][tx] = B1;
    __syncthreads();
    for (int s = 16; s > 0; s >>= 1) {
        if (ty < s) {
            #pragma unroll
            for (int a = 0; a < 8; a++) red[a][ty][tx] += red[a][ty + s][tx];
        }
        __syncthreads();
    }
    if (ty == 0 && valid) {
        float Sv = red[0][0][tx], S2v = red[1][0][tx];
        float a0 = red[2][0][tx], a1  = red[3][0][tx];
        float g0 = red[4][0][tx], g1  = red[5][0][tx];
        float b0 = red[6][0][tx], b1  = red[7][0][tx];
        float m   = Sv * (1.0f / DMODEL);
        float var = S2v * (1.0f / DMODEL) - m * m;
        float r   = rsqrtf(var + 1e-5f);
        float o0  = r * (a0 - m * g0) + b0 + qa_b[0];
        float o1  = r * (a1 - m * g1) + b1 + qa_b[1];
        out[b * LSEQ + l]            = o0;
        out[2 * LSEQ + b * LSEQ + l] = o1;
    }
}

// ---------------- host launcher ----------------
extern "C" void kernel_launch(void* const* d_in, const int* in_sizes, int n_in,
                              void* d_out, int out_size) {
    const int*   ids  = (const int*)  d_in[0];
    const float* emb  = (const float*)d_in[1];
    const float* pos  = (const float*)d_in[2];
    const float* fw   = (const float*)d_in[3];
    const float* fb   = (const float*)d_in[4];
    const float* lng  = (const float*)d_in[5];
    const float* lnb  = (const float*)d_in[6];
    const float* qaw  = (const float*)d_in[7];
    const float* qab  = (const float*)d_in[8];
    float* out = (float*)d_out;

    cudaFuncSetAttribute(wspec_kernel,    cudaFuncAttributeMaxDynamicSharedMemorySize, WSPEC_SMEM);
    cudaFuncSetAttribute(conv_all_kernel, cudaFuncAttributeMaxDynamicSharedMemorySize, CONV_SMEM);

    tw_init_kernel<<<1, 512>>>();
    embed_kernel<<<dim3(128, DMODEL / 32), dim3(32, 32)>>>(ids, emb, pos);
    wspec_kernel<<<NLAYERS * (DMODEL / 2), TTHR, WSPEC_SMEM>>>(fw);
    conv_all_kernel<<<DMODEL, TTHR, CONV_SMEM>>>(fb);
    final_kernel<<<dim3(128, 2), dim3(32, 32)>>>(lng, lnb, qaw, qab, out);
}